// round 14
// baseline (speedup 1.0000x reference)
#include <cuda_runtime.h>
#include <cuda_fp16.h>
#include <cstdint>
#include <cstddef>

// ============================================================================
// Fused LSTM cell, sm_103: fp16 mma.m16n8k16 + ldmatrix.
//  R14: CTA 256x128 (8 warps, warp tile 64x64, 1 CTA/SM) -- R9's tile economy
//  (LDSM bytes/MAC -33%) combined with R10's decoupled mbarrier pipeline (the
//  collective-barrier failure mode of R9 is gone). NST=4 deep, 192KB smem.
// ============================================================================

#define BATCH 16384
#define HID   512
#define KD    1024
#define BK    64
#define NST   4
#define NITER (KD / BK)            // 16
#define STAGE_BYTES 49152          // A 256x64 fp16 (32KB) + B 128x64 (16KB)
#define B_OFF       32768
#define PIPE_OFF    196608
#define DYN_BYTES   (196608 + 64)

__device__ __align__(256) __half g_A16[(size_t)BATCH * KD];     // 32 MB
__device__ __align__(256) __half g_W16[(size_t)2048  * KD];     // 4 MB

// ---------------------------------------------------------------------------
__device__ __forceinline__ uint32_t s2u(const void* p) {
    uint32_t a;
    asm("{ .reg .u64 t; cvta.to.shared.u64 t, %1; cvt.u32.u64 %0, t; }"
        : "=r"(a) : "l"(p));
    return a;
}
__device__ __forceinline__ void cp16(uint32_t dst, const void* src) {
    asm volatile("cp.async.cg.shared.global [%0], [%1], 16;"
                 :: "r"(dst), "l"(src));
}
__device__ __forceinline__ void ldm_x4(uint32_t* d, uint32_t a) {
    asm volatile("ldmatrix.sync.aligned.m8n8.x4.shared.b16 {%0,%1,%2,%3}, [%4];"
                 : "=r"(d[0]), "=r"(d[1]), "=r"(d[2]), "=r"(d[3]) : "r"(a));
}
__device__ __forceinline__ void mma16816(float* d, const uint32_t* a,
                                         const uint32_t* b) {
    asm volatile(
        "mma.sync.aligned.m16n8k16.row.col.f32.f16.f16.f32 "
        "{%0,%1,%2,%3}, {%4,%5,%6,%7}, {%8,%9}, {%0,%1,%2,%3};"
        : "+f"(d[0]), "+f"(d[1]), "+f"(d[2]), "+f"(d[3])
        : "r"(a[0]), "r"(a[1]), "r"(a[2]), "r"(a[3]), "r"(b[0]), "r"(b[1]));
}
__device__ __forceinline__ void bar_init(uint32_t bar, uint32_t cnt) {
    asm volatile("mbarrier.init.shared.b64 [%0], %1;" :: "r"(bar), "r"(cnt)
                 : "memory");
}
__device__ __forceinline__ void bar_wait(uint32_t bar, uint32_t parity) {
    asm volatile(
        "{\n\t.reg .pred P;\n\t"
        "WL%=:\n\t"
        "mbarrier.try_wait.parity.shared.b64 P, [%0], %1;\n\t"
        "@P bra WD%=;\n\t"
        "bra WL%=;\n\t"
        "WD%=:\n\t}"
        :: "r"(bar), "r"(parity) : "memory");
}
__device__ __forceinline__ void bar_arrive(uint32_t bar) {
    asm volatile("mbarrier.arrive.shared.b64 _, [%0];" :: "r"(bar) : "memory");
}
__device__ __forceinline__ void cp_arrive_noinc(uint32_t bar) {
    asm volatile("cp.async.mbarrier.arrive.noinc.shared.b64 [%0];"
                 :: "r"(bar) : "memory");
}
__device__ __forceinline__ float sigmoid_f(float x) {
    return 1.0f / (1.0f + __expf(-x));
}
__device__ __forceinline__ float tanh_f(float x) {
    float e = __expf(2.0f * x);
    return 1.0f - 2.0f / (e + 1.0f);
}

// ---------------------------------------------------------------------------
// merged pre-pass: blocks [0,4096) convert A, blocks [4096,4608) convert W.
__global__ void __launch_bounds__(256) convAW(const float* __restrict__ ph,
                                              const float* __restrict__ xin,
                                              const float* __restrict__ Wi,
                                              const float* __restrict__ Wf,
                                              const float* __restrict__ Wo,
                                              const float* __restrict__ Wg) {
    if (blockIdx.x < 4096) {
        const size_t idx = (size_t)blockIdx.x * 256 + threadIdx.x;  // 1M thr
        #pragma unroll
        for (int j = 0; j < 4; ++j) {
            const size_t i = idx + (size_t)j * 1048576;             // 4M groups
            const int row = (int)(i >> 8);
            const int col = (int)(i & 255) * 4;
            const float* s = (col < 512) ? (ph + (size_t)row * 512 + col)
                                         : (xin + (size_t)row * 512 + (col - 512));
            const float4 v = *(const float4*)s;
            __half2 h0 = __floats2half2_rn(v.x, v.y);
            __half2 h1 = __floats2half2_rn(v.z, v.w);
            uint2 u;
            u.x = *reinterpret_cast<uint32_t*>(&h0);
            u.y = *reinterpret_cast<uint32_t*>(&h1);
            *(uint2*)(g_A16 + i * 4) = u;
        }
    } else {
        const size_t idx = (size_t)(blockIdx.x - 4096) * 256 + threadIdx.x;
        #pragma unroll
        for (int j = 0; j < 4; ++j) {
            const size_t i = idx + (size_t)j * 131072;              // 512K groups
            const int orow = (int)(i >> 8);
            const int col  = (int)(i & 255) * 4;
            const int ht = orow >> 7, r = orow & 127;
            // gate-interleaved: gate = bits[3:4], h = b6*16 + b5*8 + b[0:2]
            const int gate = (r >> 3) & 3;
            const int h    = ((r >> 6) << 4) + (((r >> 5) & 1) << 3) + (r & 7);
            const int hrow = ht * 32 + h;
            const float* W = (gate == 0) ? Wi : (gate == 1) ? Wf
                           : (gate == 2) ? Wo : Wg;
            const float4 v = *(const float4*)(W + (size_t)hrow * KD + col);
            __half2 h0 = __floats2half2_rn(v.x, v.y);
            __half2 h1 = __floats2half2_rn(v.z, v.w);
            uint2 u;
            u.x = *reinterpret_cast<uint32_t*>(&h0);
            u.y = *reinterpret_cast<uint32_t*>(&h1);
            *(uint2*)(g_W16 + i * 4) = u;
        }
    }
}

// ---------------------------------------------------------------------------
__global__ void __launch_bounds__(256, 1)
lstm_fp16_gemm(const float* __restrict__ prev_c,
               const float* __restrict__ bi, const float* __restrict__ bf,
               const float* __restrict__ bo, const float* __restrict__ bg,
               float* __restrict__ h_out, float* __restrict__ c_out)
{
    extern __shared__ char smc[];
    const uint32_t sb = s2u(smc);
    const uint32_t FULLB  = sb + PIPE_OFF;
    const uint32_t EMPTYB = sb + PIPE_OFF + 32;

    const int tid = threadIdx.x;
    const int wid = tid >> 5;
    const int lid = tid & 31;
    const int hb  = blockIdx.x;            // 16 h-tiles
    const int mb  = blockIdx.y;            // 64 m-tiles (256 rows)
    const int wm  = wid >> 1;              // 0..3 : 64 m-rows per warp
    const int wn  = wid & 1;               // 0..1 : 64 n-cols per warp

    if (tid == 0) {
        #pragma unroll
        for (int s = 0; s < NST; ++s) {
            bar_init(FULLB  + 8 * s, 256);
            bar_init(EMPTYB + 8 * s, 256);
        }
    }
    __syncthreads();

    // ---- producer mapping: 8 threads per 128B row ---------------------------
    const int cr = tid >> 3;               // 0..31
    const int cc = tid & 7;                // chunk 0..7
    const uint32_t off_cp = (uint32_t)(cr * 128 + ((cc ^ (cr & 7)) << 4));
    const __half* gA = g_A16 + (size_t)(mb * 256) * KD + cc * 8;
    const __half* gB = g_W16 + (size_t)(hb * 128) * KD + cc * 8;

    auto produce = [&](int kt) {
        const int s2 = kt % NST;
        const uint32_t so = sb + (uint32_t)s2 * STAGE_BYTES + off_cp;
        const int kcol = kt * BK;
        #pragma unroll
        for (int i = 0; i < 8; ++i) {      // A: 256 rows
            const int r = cr + 32 * i;
            cp16(so + i * 4096, gA + (size_t)r * KD + kcol);
        }
        #pragma unroll
        for (int i = 0; i < 4; ++i) {      // B: 128 rows
            const int r = cr + 32 * i;
            cp16(so + B_OFF + i * 4096, gB + (size_t)r * KD + kcol);
        }
        cp_arrive_noinc(FULLB + 8 * s2);
    };

    produce(0);
    produce(1);
    produce(2);

    // ---- accumulators pre-loaded with biases --------------------------------
    // fragment ni: gate = ni&3 (i,f,o,g), h_octet = wn*2 + (ni>>2)
    float acc[4][8][4];
    {
        const int hq = hb * 32 + (lid & 3) * 2;
        #pragma unroll
        for (int ni = 0; ni < 8; ++ni) {
            const int gate = ni & 3;
            const int h = hq + ((wn * 2 + (ni >> 2)) << 3);
            const float* bp = (gate == 0) ? bi : (gate == 1) ? bf
                            : (gate == 2) ? bo : bg;
            const float b0 = __ldg(&bp[h]);
            const float b1 = __ldg(&bp[h + 1]);
            #pragma unroll
            for (int mi = 0; mi < 4; ++mi) {
                acc[mi][ni][0] = b0; acc[mi][ni][1] = b1;
                acc[mi][ni][2] = b0; acc[mi][ni][3] = b1;
            }
        }
    }

    // ---- XOR-folded ldmatrix base offsets -----------------------------------
    const int a_r = (lid & 15);
    const int a_c = (lid >> 4);
    const int b_r = ((lid >> 4) << 3) + (lid & 7);
    const int b_c = ((lid >> 3) & 1);
    uint32_t offA[4], offB[4];
    #pragma unroll
    for (int mi = 0; mi < 4; ++mi) {
        const int r = wm * 64 + mi * 16 + a_r;
        offA[mi] = (uint32_t)(r * 128 + ((a_c ^ (r & 7)) << 4));
    }
    #pragma unroll
    for (int n2 = 0; n2 < 4; ++n2) {
        const int r = wn * 64 + n2 * 16 + b_r;
        offB[n2] = (uint32_t)(B_OFF + r * 128 + ((b_c ^ (r & 7)) << 4));
    }

    uint32_t a[2][4][4], b[2][8][2];       // double-buffered fragments

    auto preload = [&](int buf, uint32_t stage_base, int ks) {
        const uint32_t x = (uint32_t)(ks << 5);
        #pragma unroll
        for (int mi = 0; mi < 4; ++mi)
            ldm_x4(a[buf][mi], stage_base + (offA[mi] ^ x));
        #pragma unroll
        for (int n2 = 0; n2 < 4; ++n2) {
            uint32_t t4[4];
            ldm_x4(t4, stage_base + (offB[n2] ^ x));
            b[buf][n2 * 2][0] = t4[0]; b[buf][n2 * 2][1] = t4[1];
            b[buf][n2 * 2 + 1][0] = t4[2]; b[buf][n2 * 2 + 1][1] = t4[3];
        }
    };

    #pragma unroll 1
    for (int it = 0; it < NITER; ++it) {
        const int s = it % NST;
        const int u = it / NST;

        // producer for stage it+3 (NST-1 lookahead)
        if (it + 3 < NITER) {
            const int i3 = it + 3;
            if (i3 >= NST)
                bar_wait(EMPTYB + 8 * (i3 % NST), ((i3 / NST) - 1) & 1);
            produce(i3);
        }

        bar_wait(FULLB + 8 * s, u & 1);
        const uint32_t smA = sb + (uint32_t)s * STAGE_BYTES;

        preload(0, smA, 0);
        #pragma unroll
        for (int ks = 0; ks < 4; ++ks) {
            const int cur = ks & 1, nxt = cur ^ 1;
            if (ks < 3) preload(nxt, smA, ks + 1);
            #pragma unroll
            for (int mi = 0; mi < 4; ++mi)
                #pragma unroll
                for (int ni = 0; ni < 8; ++ni)
                    mma16816(acc[mi][ni], a[cur][mi], b[cur][ni]);
        }
        bar_arrive(EMPTYB + 8 * s);
    }

    // ---- register-local epilogue --------------------------------------------
    #pragma unroll
    for (int mi = 0; mi < 4; ++mi) {
        const int r_base = mb * 256 + wm * 64 + mi * 16 + (lid >> 2);
        #pragma unroll
        for (int ho = 0; ho < 2; ++ho) {
            const int hg = hb * 32 + ((wn * 2 + ho) << 3) + (lid & 3) * 2;
            #pragma unroll
            for (int pr = 0; pr < 2; ++pr) {
                const int r = r_base + pr * 8;
                const size_t off = (size_t)r * HID + hg;
                const float2 pc = *(const float2*)(prev_c + off);
                const int q0 = pr * 2, q1 = pr * 2 + 1;
                const float i0 = sigmoid_f(acc[mi][ho * 4 + 0][q0]);
                const float f0 = sigmoid_f(acc[mi][ho * 4 + 1][q0]);
                const float o0 = sigmoid_f(acc[mi][ho * 4 + 2][q0]);
                const float g0 = tanh_f   (acc[mi][ho * 4 + 3][q0]);
                const float i1 = sigmoid_f(acc[mi][ho * 4 + 0][q1]);
                const float f1 = sigmoid_f(acc[mi][ho * 4 + 1][q1]);
                const float o1 = sigmoid_f(acc[mi][ho * 4 + 2][q1]);
                const float g1 = tanh_f   (acc[mi][ho * 4 + 3][q1]);
                const float c0 = f0 * pc.x + i0 * g0;
                const float c1 = f1 * pc.y + i1 * g1;
                *(float2*)(h_out + off) = make_float2(tanh_f(c0) * o0,
                                                      tanh_f(c1) * o1);
                *(float2*)(c_out + off) = make_float2(c0, c1);
            }
        }
    }
}

// ---------------------------------------------------------------------------
extern "C" void kernel_launch(void* const* d_in, const int* in_sizes, int n_in,
                              void* d_out, int out_size) {
    const float* input_ = (const float*)d_in[0];
    const float* prev_h = (const float*)d_in[1];
    const float* prev_c = (const float*)d_in[2];
    const float* W_i = (const float*)d_in[3];  const float* b_i = (const float*)d_in[4];
    const float* W_f = (const float*)d_in[5];  const float* b_f = (const float*)d_in[6];
    const float* W_g = (const float*)d_in[7];  const float* b_g = (const float*)d_in[8];
    const float* W_o = (const float*)d_in[9];  const float* b_o = (const float*)d_in[10];

    float* h_out = (float*)d_out;
    float* c_out = h_out + (size_t)BATCH * HID;

    convAW<<<4608, 256>>>(prev_h, input_, W_i, W_f, W_o, W_g);

    cudaFuncSetAttribute(lstm_fp16_gemm,
                         cudaFuncAttributeMaxDynamicSharedMemorySize, DYN_BYTES);
    dim3 grid(16, 64);
    lstm_fp16_gemm<<<grid, 256, DYN_BYTES>>>(prev_c, b_i, b_f, b_o, b_g,
                                             h_out, c_out);
}

// round 15
// speedup vs baseline: 1.1497x; 1.1497x over previous
#include <cuda_runtime.h>
#include <cuda_fp16.h>
#include <cstdint>
#include <cstddef>

// ============================================================================
// Fused LSTM cell, sm_103: fp16 mma.m16n8k16 + ldmatrix.
//  R15: PERSISTENT version of the R10 champion. Grid = 296 CTAs (2/SM, one
//  wave); each CTA processes ~7 tiles with a global iteration counter so the
//  full/empty mbarrier pipeline never drains across tiles: next tile's
//  cp.asyncs overlap this tile's epilogue. Inner iteration identical to R10.
// ============================================================================

#define BATCH 16384
#define HID   512
#define KD    1024
#define BK    64
#define NST   3
#define NITER (KD / BK)            // 16 per tile
#define NTILE 2048                 // 128 m-tiles x 16 h-tiles
#define NCTA  296
#define STAGE_BYTES 32768          // A 128x64 fp16 (16KB) + B (16KB)
#define PIPE_OFF    98304
#define DYN_BYTES   (98304 + 64)

__device__ __align__(256) __half g_A16[(size_t)BATCH * KD];     // 32 MB
__device__ __align__(256) __half g_W16[(size_t)2048  * KD];     // 4 MB

// ---------------------------------------------------------------------------
__device__ __forceinline__ uint32_t s2u(const void* p) {
    uint32_t a;
    asm("{ .reg .u64 t; cvta.to.shared.u64 t, %1; cvt.u32.u64 %0, t; }"
        : "=r"(a) : "l"(p));
    return a;
}
__device__ __forceinline__ void cp16(uint32_t dst, const void* src) {
    asm volatile("cp.async.cg.shared.global [%0], [%1], 16;"
                 :: "r"(dst), "l"(src));
}
__device__ __forceinline__ void ldm_x4(uint32_t* d, uint32_t a) {
    asm volatile("ldmatrix.sync.aligned.m8n8.x4.shared.b16 {%0,%1,%2,%3}, [%4];"
                 : "=r"(d[0]), "=r"(d[1]), "=r"(d[2]), "=r"(d[3]) : "r"(a));
}
__device__ __forceinline__ void mma16816(float* d, const uint32_t* a,
                                         const uint32_t* b) {
    asm volatile(
        "mma.sync.aligned.m16n8k16.row.col.f32.f16.f16.f32 "
        "{%0,%1,%2,%3}, {%4,%5,%6,%7}, {%8,%9}, {%0,%1,%2,%3};"
        : "+f"(d[0]), "+f"(d[1]), "+f"(d[2]), "+f"(d[3])
        : "r"(a[0]), "r"(a[1]), "r"(a[2]), "r"(a[3]), "r"(b[0]), "r"(b[1]));
}
__device__ __forceinline__ void bar_init(uint32_t bar, uint32_t cnt) {
    asm volatile("mbarrier.init.shared.b64 [%0], %1;" :: "r"(bar), "r"(cnt)
                 : "memory");
}
__device__ __forceinline__ void bar_wait(uint32_t bar, uint32_t parity) {
    asm volatile(
        "{\n\t.reg .pred P;\n\t"
        "WL%=:\n\t"
        "mbarrier.try_wait.parity.shared.b64 P, [%0], %1;\n\t"
        "@P bra WD%=;\n\t"
        "bra WL%=;\n\t"
        "WD%=:\n\t}"
        :: "r"(bar), "r"(parity) : "memory");
}
__device__ __forceinline__ void bar_arrive(uint32_t bar) {
    asm volatile("mbarrier.arrive.shared.b64 _, [%0];" :: "r"(bar) : "memory");
}
__device__ __forceinline__ void cp_arrive_noinc(uint32_t bar) {
    asm volatile("cp.async.mbarrier.arrive.noinc.shared.b64 [%0];"
                 :: "r"(bar) : "memory");
}
__device__ __forceinline__ float sigmoid_f(float x) {
    return 1.0f / (1.0f + __expf(-x));
}
__device__ __forceinline__ float tanh_f(float x) {
    float e = __expf(2.0f * x);
    return 1.0f - 2.0f / (e + 1.0f);
}

// ---------------------------------------------------------------------------
// merged pre-pass: blocks [0,4096) convert A, blocks [4096,4608) convert W.
__global__ void __launch_bounds__(256) convAW(const float* __restrict__ ph,
                                              const float* __restrict__ xin,
                                              const float* __restrict__ Wi,
                                              const float* __restrict__ Wf,
                                              const float* __restrict__ Wo,
                                              const float* __restrict__ Wg) {
    if (blockIdx.x < 4096) {
        const size_t idx = (size_t)blockIdx.x * 256 + threadIdx.x;  // 1M thr
        #pragma unroll
        for (int j = 0; j < 4; ++j) {
            const size_t i = idx + (size_t)j * 1048576;             // 4M groups
            const int row = (int)(i >> 8);
            const int col = (int)(i & 255) * 4;
            const float* s = (col < 512) ? (ph + (size_t)row * 512 + col)
                                         : (xin + (size_t)row * 512 + (col - 512));
            const float4 v = *(const float4*)s;
            __half2 h0 = __floats2half2_rn(v.x, v.y);
            __half2 h1 = __floats2half2_rn(v.z, v.w);
            uint2 u;
            u.x = *reinterpret_cast<uint32_t*>(&h0);
            u.y = *reinterpret_cast<uint32_t*>(&h1);
            *(uint2*)(g_A16 + i * 4) = u;
        }
    } else {
        const size_t idx = (size_t)(blockIdx.x - 4096) * 256 + threadIdx.x;
        #pragma unroll
        for (int j = 0; j < 4; ++j) {
            const size_t i = idx + (size_t)j * 131072;              // 512K groups
            const int orow = (int)(i >> 8);
            const int col  = (int)(i & 255) * 4;
            const int ht = orow >> 7, r = orow & 127;
            // gate-interleaved: gate = bits[3:4], h = b6*16 + b5*8 + b[0:2]
            const int gate = (r >> 3) & 3;
            const int h    = ((r >> 6) << 4) + (((r >> 5) & 1) << 3) + (r & 7);
            const int hrow = ht * 32 + h;
            const float* W = (gate == 0) ? Wi : (gate == 1) ? Wf
                           : (gate == 2) ? Wo : Wg;
            const float4 v = *(const float4*)(W + (size_t)hrow * KD + col);
            __half2 h0 = __floats2half2_rn(v.x, v.y);
            __half2 h1 = __floats2half2_rn(v.z, v.w);
            uint2 u;
            u.x = *reinterpret_cast<uint32_t*>(&h0);
            u.y = *reinterpret_cast<uint32_t*>(&h1);
            *(uint2*)(g_W16 + i * 4) = u;
        }
    }
}

// ---------------------------------------------------------------------------
__global__ void __launch_bounds__(256, 2)
lstm_fp16_gemm(const float* __restrict__ prev_c,
               const float* __restrict__ bi, const float* __restrict__ bf,
               const float* __restrict__ bo, const float* __restrict__ bg,
               float* __restrict__ h_out, float* __restrict__ c_out)
{
    extern __shared__ char smc[];
    const uint32_t sb = s2u(smc);
    const uint32_t FULLB  = sb + PIPE_OFF;
    const uint32_t EMPTYB = sb + PIPE_OFF + 24;

    const int tid = threadIdx.x;
    const int wid = tid >> 5;
    const int lid = tid & 31;
    const int bid = blockIdx.x;            // 0..295 persistent CTAs
    const int wm  = wid >> 1;              // 0..3
    const int wn  = wid & 1;               // 0..1

    const int ntiles = (NTILE - 1 - bid) / NCTA + 1;     // 7 or 6
    const int total  = ntiles * NITER;

    if (tid == 0) {
        #pragma unroll
        for (int s = 0; s < NST; ++s) {
            bar_init(FULLB  + 8 * s, 256);
            bar_init(EMPTYB + 8 * s, 256);
        }
    }
    __syncthreads();

    // ---- producer mapping ----------------------------------------------------
    const int cr = tid >> 3;               // 0..31
    const int cc = tid & 7;                // chunk 0..7
    const uint32_t off_cp = (uint32_t)(cr * 128 + ((cc ^ (cr & 7)) << 4));

    // produce for GLOBAL iteration index: tile j = git>>4, k-chunk kt = git&15
    auto produce = [&](int git) {
        const int g  = (git >> 4) * NCTA + bid;          // tile id
        const int kt = git & 15;
        const int s2 = git % NST;
        const int mbp = g >> 4, hbp = g & 15;
        const __half* pA = g_A16 + (size_t)(mbp * 128) * KD + cc * 8
                         + (size_t)kt * BK + (size_t)cr * KD;
        const __half* pB = g_W16 + (size_t)(hbp * 128) * KD + cc * 8
                         + (size_t)kt * BK + (size_t)cr * KD;
        const uint32_t so = sb + (uint32_t)s2 * STAGE_BYTES + off_cp;
        #pragma unroll
        for (int i = 0; i < 4; ++i) {
            cp16(so + i * 4096,         pA + (size_t)(32 * i) * KD);
            cp16(so + 16384 + i * 4096, pB + (size_t)(32 * i) * KD);
        }
        cp_arrive_noinc(FULLB + 8 * s2);
    };

    produce(0);
    produce(1);

    // ---- fragment machinery ---------------------------------------------------
    const int a_r = (lid & 15);
    const int a_c = (lid >> 4);
    const int b_r = ((lid >> 4) << 3) + (lid & 7);
    const int b_c = ((lid >> 3) & 1);
    uint32_t offA[2], offB[4];
    #pragma unroll
    for (int mi = 0; mi < 2; ++mi) {
        const int r = wm * 32 + mi * 16 + a_r;
        offA[mi] = (uint32_t)(r * 128 + ((a_c ^ (r & 7)) << 4));
    }
    #pragma unroll
    for (int n2 = 0; n2 < 4; ++n2) {
        const int r = wn * 64 + n2 * 16 + b_r;
        offB[n2] = (uint32_t)(16384 + r * 128 + ((b_c ^ (r & 7)) << 4));
    }

    uint32_t a[2][2][4], b[2][8][2];
    float acc[2][8][4];

    auto preload = [&](int buf, uint32_t stage_base, int ks) {
        const uint32_t x = (uint32_t)(ks << 5);
        #pragma unroll
        for (int mi = 0; mi < 2; ++mi)
            ldm_x4(a[buf][mi], stage_base + (offA[mi] ^ x));
        #pragma unroll
        for (int n2 = 0; n2 < 4; ++n2) {
            uint32_t t4[4];
            ldm_x4(t4, stage_base + (offB[n2] ^ x));
            b[buf][n2 * 2][0] = t4[0]; b[buf][n2 * 2][1] = t4[1];
            b[buf][n2 * 2 + 1][0] = t4[2]; b[buf][n2 * 2 + 1][1] = t4[3];
        }
    };

    #pragma unroll 1
    for (int git = 0; git < total; ++git) {
        const int s = git % NST;
        const int u = git / NST;
        const int g = (git >> 4) * NCTA + bid;           // current tile id

        // per-tile accumulator init (biases folded in)
        if ((git & 15) == 0) {
            const int hbp = g & 15;
            const int hq = hbp * 32 + wn * 16 + (lid & 3) * 2;
            #pragma unroll
            for (int ni = 0; ni < 8; ++ni) {
                const int gate = ni & 3;
                const int h = hq + ((ni >> 2) << 3);
                const float* bp = (gate == 0) ? bi : (gate == 1) ? bf
                                : (gate == 2) ? bo : bg;
                const float b0 = __ldg(&bp[h]);
                const float b1 = __ldg(&bp[h + 1]);
                #pragma unroll
                for (int mi = 0; mi < 2; ++mi) {
                    acc[mi][ni][0] = b0; acc[mi][ni][1] = b1;
                    acc[mi][ni][2] = b0; acc[mi][ni][3] = b1;
                }
            }
        }

        // producer for global iteration git+2 (may belong to the NEXT tile)
        if (git + 2 < total) {
            const int g2 = git + 2;
            if (g2 >= NST)
                bar_wait(EMPTYB + 8 * (g2 % NST), ((g2 / NST) - 1) & 1);
            produce(g2);
        }

        bar_wait(FULLB + 8 * s, u & 1);
        const uint32_t smA = sb + (uint32_t)s * STAGE_BYTES;

        preload(0, smA, 0);
        #pragma unroll
        for (int ks = 0; ks < 4; ++ks) {
            const int cur = ks & 1, nxt = cur ^ 1;
            if (ks < 3) preload(nxt, smA, ks + 1);
            #pragma unroll
            for (int mi = 0; mi < 2; ++mi)
                #pragma unroll
                for (int ni = 0; ni < 8; ++ni)
                    mma16816(acc[mi][ni], a[cur][mi], b[cur][ni]);
        }
        bar_arrive(EMPTYB + 8 * s);

        // per-tile epilogue (overlaps next tile's in-flight cp.asyncs)
        if ((git & 15) == 15) {
            const int mbp = g >> 4, hbp = g & 15;
            #pragma unroll
            for (int mi = 0; mi < 2; ++mi) {
                const int r_base = mbp * 128 + wm * 32 + mi * 16 + (lid >> 2);
                #pragma unroll
                for (int ho = 0; ho < 2; ++ho) {
                    const int hg = hbp * 32 + wn * 16 + ho * 8 + (lid & 3) * 2;
                    #pragma unroll
                    for (int pr = 0; pr < 2; ++pr) {
                        const int r = r_base + pr * 8;
                        const size_t off = (size_t)r * HID + hg;
                        const float2 pc = *(const float2*)(prev_c + off);
                        const int q0 = pr * 2, q1 = pr * 2 + 1;
                        const float i0 = sigmoid_f(acc[mi][ho * 4 + 0][q0]);
                        const float f0 = sigmoid_f(acc[mi][ho * 4 + 1][q0]);
                        const float o0 = sigmoid_f(acc[mi][ho * 4 + 2][q0]);
                        const float g0 = tanh_f   (acc[mi][ho * 4 + 3][q0]);
                        const float i1 = sigmoid_f(acc[mi][ho * 4 + 0][q1]);
                        const float f1 = sigmoid_f(acc[mi][ho * 4 + 1][q1]);
                        const float o1 = sigmoid_f(acc[mi][ho * 4 + 2][q1]);
                        const float g1 = tanh_f   (acc[mi][ho * 4 + 3][q1]);
                        const float c0 = f0 * pc.x + i0 * g0;
                        const float c1 = f1 * pc.y + i1 * g1;
                        *(float2*)(h_out + off) = make_float2(tanh_f(c0) * o0,
                                                              tanh_f(c1) * o1);
                        *(float2*)(c_out + off) = make_float2(c0, c1);
                    }
                }
            }
        }
    }
}

// ---------------------------------------------------------------------------
extern "C" void kernel_launch(void* const* d_in, const int* in_sizes, int n_in,
                              void* d_out, int out_size) {
    const float* input_ = (const float*)d_in[0];
    const float* prev_h = (const float*)d_in[1];
    const float* prev_c = (const float*)d_in[2];
    const float* W_i = (const float*)d_in[3];  const float* b_i = (const float*)d_in[4];
    const float* W_f = (const float*)d_in[5];  const float* b_f = (const float*)d_in[6];
    const float* W_g = (const float*)d_in[7];  const float* b_g = (const float*)d_in[8];
    const float* W_o = (const float*)d_in[9];  const float* b_o = (const float*)d_in[10];

    float* h_out = (float*)d_out;
    float* c_out = h_out + (size_t)BATCH * HID;

    convAW<<<4608, 256>>>(prev_h, input_, W_i, W_f, W_o, W_g);

    cudaFuncSetAttribute(lstm_fp16_gemm,
                         cudaFuncAttributeMaxDynamicSharedMemorySize, DYN_BYTES);
    lstm_fp16_gemm<<<NCTA, 256, DYN_BYTES>>>(prev_c, b_i, b_f, b_o, b_g,
                                             h_out, c_out);
}

// round 16
// speedup vs baseline: 1.2324x; 1.0719x over previous
#include <cuda_runtime.h>
#include <cuda_fp16.h>
#include <cstdint>
#include <cstddef>

// ============================================================================
// Fused LSTM cell, sm_103: fp16 mma.m16n8k16 + ldmatrix.
//  R16: GEMM byte-identical to the R10 champion (CTA 128x128, warp 32x64,
//  8 warps, 2 CTA/SM, mbarrier full/empty pipeline, NST=3, BK=64).
//  convAW: A-path now 8 independent units/thread (MLP 4 -> 8) to push the
//  latency-bound pre-pass toward the DRAM roofline.
// ============================================================================

#define BATCH 16384
#define HID   512
#define KD    1024
#define BK    64
#define NST   3
#define NITER (KD / BK)            // 16
#define STAGE_BYTES 32768          // A 128x64 fp16 (16KB) + B (16KB)
#define PIPE_OFF    98304
#define DYN_BYTES   (98304 + 64)

__device__ __align__(256) __half g_A16[(size_t)BATCH * KD];     // 32 MB
__device__ __align__(256) __half g_W16[(size_t)2048  * KD];     // 4 MB

// ---------------------------------------------------------------------------
__device__ __forceinline__ uint32_t s2u(const void* p) {
    uint32_t a;
    asm("{ .reg .u64 t; cvta.to.shared.u64 t, %1; cvt.u32.u64 %0, t; }"
        : "=r"(a) : "l"(p));
    return a;
}
__device__ __forceinline__ void cp16(uint32_t dst, const void* src) {
    asm volatile("cp.async.cg.shared.global [%0], [%1], 16;"
                 :: "r"(dst), "l"(src));
}
__device__ __forceinline__ void ldm_x4(uint32_t* d, uint32_t a) {
    asm volatile("ldmatrix.sync.aligned.m8n8.x4.shared.b16 {%0,%1,%2,%3}, [%4];"
                 : "=r"(d[0]), "=r"(d[1]), "=r"(d[2]), "=r"(d[3]) : "r"(a));
}
__device__ __forceinline__ void mma16816(float* d, const uint32_t* a,
                                         const uint32_t* b) {
    asm volatile(
        "mma.sync.aligned.m16n8k16.row.col.f32.f16.f16.f32 "
        "{%0,%1,%2,%3}, {%4,%5,%6,%7}, {%8,%9}, {%0,%1,%2,%3};"
        : "+f"(d[0]), "+f"(d[1]), "+f"(d[2]), "+f"(d[3])
        : "r"(a[0]), "r"(a[1]), "r"(a[2]), "r"(a[3]), "r"(b[0]), "r"(b[1]));
}
__device__ __forceinline__ void bar_init(uint32_t bar, uint32_t cnt) {
    asm volatile("mbarrier.init.shared.b64 [%0], %1;" :: "r"(bar), "r"(cnt)
                 : "memory");
}
__device__ __forceinline__ void bar_wait(uint32_t bar, uint32_t parity) {
    asm volatile(
        "{\n\t.reg .pred P;\n\t"
        "WL%=:\n\t"
        "mbarrier.try_wait.parity.shared.b64 P, [%0], %1;\n\t"
        "@P bra WD%=;\n\t"
        "bra WL%=;\n\t"
        "WD%=:\n\t}"
        :: "r"(bar), "r"(parity) : "memory");
}
__device__ __forceinline__ void bar_arrive(uint32_t bar) {
    asm volatile("mbarrier.arrive.shared.b64 _, [%0];" :: "r"(bar) : "memory");
}
__device__ __forceinline__ void cp_arrive_noinc(uint32_t bar) {
    asm volatile("cp.async.mbarrier.arrive.noinc.shared.b64 [%0];"
                 :: "r"(bar) : "memory");
}
__device__ __forceinline__ float sigmoid_f(float x) {
    return 1.0f / (1.0f + __expf(-x));
}
__device__ __forceinline__ float tanh_f(float x) {
    float e = __expf(2.0f * x);
    return 1.0f - 2.0f / (e + 1.0f);
}
// smem byte offset for (row, 16B-chunk), rows are 128B (8 chunks), xor swizzle
__device__ __forceinline__ uint32_t sw(int r, int c) {
    return (uint32_t)(r * 128 + ((c ^ (r & 7)) << 4));
}

// ---------------------------------------------------------------------------
// merged pre-pass: blocks [0,2048) convert A (8 units/thread, MLP 8),
// blocks [2048,2560) convert W (4 units/thread).
__global__ void __launch_bounds__(256) convAW(const float* __restrict__ ph,
                                              const float* __restrict__ xin,
                                              const float* __restrict__ Wi,
                                              const float* __restrict__ Wf,
                                              const float* __restrict__ Wo,
                                              const float* __restrict__ Wg) {
    if (blockIdx.x < 2048) {
        const size_t idx = (size_t)blockIdx.x * 256 + threadIdx.x;  // 512K thr
        #pragma unroll
        for (int j = 0; j < 8; ++j) {
            const size_t i = idx + (size_t)j * 524288;              // 4M groups
            const int row = (int)(i >> 8);
            const int col = (int)(i & 255) * 4;
            const float* s = (col < 512) ? (ph + (size_t)row * 512 + col)
                                         : (xin + (size_t)row * 512 + (col - 512));
            const float4 v = *(const float4*)s;
            __half2 h0 = __floats2half2_rn(v.x, v.y);
            __half2 h1 = __floats2half2_rn(v.z, v.w);
            uint2 u;
            u.x = *reinterpret_cast<uint32_t*>(&h0);
            u.y = *reinterpret_cast<uint32_t*>(&h1);
            *(uint2*)(g_A16 + i * 4) = u;
        }
    } else {
        const size_t idx = (size_t)(blockIdx.x - 2048) * 256 + threadIdx.x;
        #pragma unroll
        for (int j = 0; j < 4; ++j) {
            const size_t i = idx + (size_t)j * 131072;              // 512K groups
            const int orow = (int)(i >> 8);
            const int col  = (int)(i & 255) * 4;
            const int ht = orow >> 7, r = orow & 127;
            // gate-interleaved: gate = bits[3:4], h = b6*16 + b5*8 + b[0:2]
            const int gate = (r >> 3) & 3;
            const int h    = ((r >> 6) << 4) + (((r >> 5) & 1) << 3) + (r & 7);
            const int hrow = ht * 32 + h;
            const float* W = (gate == 0) ? Wi : (gate == 1) ? Wf
                           : (gate == 2) ? Wo : Wg;
            const float4 v = *(const float4*)(W + (size_t)hrow * KD + col);
            __half2 h0 = __floats2half2_rn(v.x, v.y);
            __half2 h1 = __floats2half2_rn(v.z, v.w);
            uint2 u;
            u.x = *reinterpret_cast<uint32_t*>(&h0);
            u.y = *reinterpret_cast<uint32_t*>(&h1);
            *(uint2*)(g_W16 + i * 4) = u;
        }
    }
}

// ---------------------------------------------------------------------------
__global__ void __launch_bounds__(256, 2)
lstm_fp16_gemm(const float* __restrict__ prev_c,
               const float* __restrict__ bi, const float* __restrict__ bf,
               const float* __restrict__ bo, const float* __restrict__ bg,
               float* __restrict__ h_out, float* __restrict__ c_out)
{
    extern __shared__ char smc[];
    const uint32_t sb = s2u(smc);
    const uint32_t FULLB  = sb + PIPE_OFF;        // full[s]  at +0,8,16
    const uint32_t EMPTYB = sb + PIPE_OFF + 24;   // empty[s] at +0,8,16

    const int tid = threadIdx.x;
    const int wid = tid >> 5;
    const int lid = tid & 31;
    const int hb  = blockIdx.x;            // 16 h-tiles (fastest: W hot in L2)
    const int mb  = blockIdx.y;            // 128 m-tiles
    const int wm  = wid >> 1;              // 0..3
    const int wn  = wid & 1;               // 0..1

    if (tid == 0) {
        #pragma unroll
        for (int s = 0; s < NST; ++s) {
            bar_init(FULLB  + 8 * s, 256);
            bar_init(EMPTYB + 8 * s, 256);
        }
    }
    __syncthreads();

    // ---- cp.async mapping: 8 threads cover one 128B row ---------------------
    const int cr = tid >> 3;               // 0..31
    const int cc = tid & 7;                // chunk 0..7
    const __half* gA = g_A16 + (size_t)(mb * 128) * KD + cc * 8;
    const __half* gB = g_W16 + (size_t)(hb * 128) * KD + cc * 8;

    auto produce = [&](int kt) {
        const int s2 = kt % NST;
        const uint32_t so = sb + (uint32_t)s2 * STAGE_BYTES;
        const int kcol = kt * BK;
        #pragma unroll
        for (int i = 0; i < 4; ++i) {
            const int r = cr + 32 * i;
            cp16(so + sw(r, cc),         gA + (size_t)r * KD + kcol);
            cp16(so + 16384 + sw(r, cc), gB + (size_t)r * KD + kcol);
        }
        cp_arrive_noinc(FULLB + 8 * s2);
    };

    produce(0);
    produce(1);

    // ---- accumulators pre-loaded with biases --------------------------------
    float acc[2][8][4];
    {
        const int hq = hb * 32 + wn * 16 + (lid & 3) * 2;
        #pragma unroll
        for (int ni = 0; ni < 8; ++ni) {
            const int gate = ni & 3;
            const int h = hq + ((ni >> 2) << 3);
            const float* bp = (gate == 0) ? bi : (gate == 1) ? bf
                            : (gate == 2) ? bo : bg;
            const float b0 = __ldg(&bp[h]);
            const float b1 = __ldg(&bp[h + 1]);
            #pragma unroll
            for (int mi = 0; mi < 2; ++mi) {
                acc[mi][ni][0] = b0; acc[mi][ni][1] = b1;
                acc[mi][ni][2] = b0; acc[mi][ni][3] = b1;
            }
        }
    }

    // ldmatrix lane coordinates
    const int a_r = (lid & 15);
    const int a_c = (lid >> 4);
    const int b_r = ((lid >> 4) << 3) + (lid & 7);
    const int b_c = ((lid >> 3) & 1);

    #pragma unroll 1
    for (int it = 0; it < NITER; ++it) {
        const int s = it % NST;
        const int u = it / NST;

        // producer for stage it+2 (wait for stage free, then fill)
        if (it + 2 < NITER) {
            const int i2 = it + 2;
            if (i2 >= NST) {
                const int u2 = i2 / NST;
                bar_wait(EMPTYB + 8 * (i2 % NST), (u2 - 1) & 1);
            }
            produce(i2);
        }

        // consumer: wait until ALL threads' copies for stage s landed
        bar_wait(FULLB + 8 * s, u & 1);

        const uint32_t smA = sb + (uint32_t)s * STAGE_BYTES;
        const uint32_t smB = smA + 16384;

        uint32_t a[2][2][4], b[2][8][2];   // double-buffered fragments
        {
            #pragma unroll
            for (int mi = 0; mi < 2; ++mi)
                ldm_x4(a[0][mi], smA + sw(wm * 32 + mi * 16 + a_r, a_c));
            #pragma unroll
            for (int n2 = 0; n2 < 4; ++n2) {
                uint32_t t4[4];
                ldm_x4(t4, smB + sw(wn * 64 + n2 * 16 + b_r, b_c));
                b[0][n2 * 2][0] = t4[0]; b[0][n2 * 2][1] = t4[1];
                b[0][n2 * 2 + 1][0] = t4[2]; b[0][n2 * 2 + 1][1] = t4[3];
            }
        }
        #pragma unroll
        for (int ks = 0; ks < 4; ++ks) {
            const int cur = ks & 1, nxt = cur ^ 1;
            if (ks < 3) {                  // preload ks+1 while mma'ing ks
                const int kc = (ks + 1) * 2;
                #pragma unroll
                for (int mi = 0; mi < 2; ++mi)
                    ldm_x4(a[nxt][mi], smA + sw(wm * 32 + mi * 16 + a_r, kc + a_c));
                #pragma unroll
                for (int n2 = 0; n2 < 4; ++n2) {
                    uint32_t t4[4];
                    ldm_x4(t4, smB + sw(wn * 64 + n2 * 16 + b_r, kc + b_c));
                    b[nxt][n2 * 2][0] = t4[0]; b[nxt][n2 * 2][1] = t4[1];
                    b[nxt][n2 * 2 + 1][0] = t4[2]; b[nxt][n2 * 2 + 1][1] = t4[3];
                }
            }
            #pragma unroll
            for (int mi = 0; mi < 2; ++mi)
                #pragma unroll
                for (int ni = 0; ni < 8; ++ni)
                    mma16816(acc[mi][ni], a[cur][mi], b[cur][ni]);
        }
        // all smem reads of stage s are complete (MMAs consumed the LDSM regs)
        bar_arrive(EMPTYB + 8 * s);
    }

    // ---- register-local epilogue --------------------------------------------
    #pragma unroll
    for (int mi = 0; mi < 2; ++mi) {
        const int r_base = mb * 128 + wm * 32 + mi * 16 + (lid >> 2);
        #pragma unroll
        for (int ho = 0; ho < 2; ++ho) {
            const int hg = hb * 32 + wn * 16 + ho * 8 + (lid & 3) * 2;
            #pragma unroll
            for (int pr = 0; pr < 2; ++pr) {       // row +0 / +8
                const int r = r_base + pr * 8;
                const size_t off = (size_t)r * HID + hg;
                const float2 pc = *(const float2*)(prev_c + off);
                const int q0 = pr * 2, q1 = pr * 2 + 1;
                const float i0 = sigmoid_f(acc[mi][ho * 4 + 0][q0]);
                const float f0 = sigmoid_f(acc[mi][ho * 4 + 1][q0]);
                const float o0 = sigmoid_f(acc[mi][ho * 4 + 2][q0]);
                const float g0 = tanh_f   (acc[mi][ho * 4 + 3][q0]);
                const float i1 = sigmoid_f(acc[mi][ho * 4 + 0][q1]);
                const float f1 = sigmoid_f(acc[mi][ho * 4 + 1][q1]);
                const float o1 = sigmoid_f(acc[mi][ho * 4 + 2][q1]);
                const float g1 = tanh_f   (acc[mi][ho * 4 + 3][q1]);
                const float c0 = f0 * pc.x + i0 * g0;
                const float c1 = f1 * pc.y + i1 * g1;
                *(float2*)(h_out + off) = make_float2(tanh_f(c0) * o0,
                                                      tanh_f(c1) * o1);
                *(float2*)(c_out + off) = make_float2(c0, c1);
            }
        }
    }
}

// ---------------------------------------------------------------------------
extern "C" void kernel_launch(void* const* d_in, const int* in_sizes, int n_in,
                              void* d_out, int out_size) {
    const float* input_ = (const float*)d_in[0];
    const float* prev_h = (const float*)d_in[1];
    const float* prev_c = (const float*)d_in[2];
    const float* W_i = (const float*)d_in[3];  const float* b_i = (const float*)d_in[4];
    const float* W_f = (const float*)d_in[5];  const float* b_f = (const float*)d_in[6];
    const float* W_g = (const float*)d_in[7];  const float* b_g = (const float*)d_in[8];
    const float* W_o = (const float*)d_in[9];  const float* b_o = (const float*)d_in[10];

    float* h_out = (float*)d_out;
    float* c_out = h_out + (size_t)BATCH * HID;

    convAW<<<2560, 256>>>(prev_h, input_, W_i, W_f, W_o, W_g);

    cudaFuncSetAttribute(lstm_fp16_gemm,
                         cudaFuncAttributeMaxDynamicSharedMemorySize, DYN_BYTES);
    dim3 grid(16, 128);
    lstm_fp16_gemm<<<grid, 256, DYN_BYTES>>>(prev_c, b_i, b_f, b_o, b_g,
                                             h_out, c_out);
}

// round 17
// speedup vs baseline: 1.2346x; 1.0019x over previous
#include <cuda_runtime.h>
#include <cuda_fp16.h>
#include <cstdint>
#include <cstddef>

// ============================================================================
// Fused LSTM cell, sm_103: fp16 mma.m16n8k16 + ldmatrix.
//  R17: GEMM byte-identical to the R10/R16 champion. convAW restructured to
//  8-float units: 2x float4 loads -> 4x half2 cvt -> ONE 16B store (STG.128),
//  halving store count and per-byte issue slots; MLP 8 kept.
// ============================================================================

#define BATCH 16384
#define HID   512
#define KD    1024
#define BK    64
#define NST   3
#define NITER (KD / BK)            // 16
#define STAGE_BYTES 32768          // A 128x64 fp16 (16KB) + B (16KB)
#define PIPE_OFF    98304
#define DYN_BYTES   (98304 + 64)

__device__ __align__(256) __half g_A16[(size_t)BATCH * KD];     // 32 MB
__device__ __align__(256) __half g_W16[(size_t)2048  * KD];     // 4 MB

// ---------------------------------------------------------------------------
__device__ __forceinline__ uint32_t s2u(const void* p) {
    uint32_t a;
    asm("{ .reg .u64 t; cvta.to.shared.u64 t, %1; cvt.u32.u64 %0, t; }"
        : "=r"(a) : "l"(p));
    return a;
}
__device__ __forceinline__ void cp16(uint32_t dst, const void* src) {
    asm volatile("cp.async.cg.shared.global [%0], [%1], 16;"
                 :: "r"(dst), "l"(src));
}
__device__ __forceinline__ void ldm_x4(uint32_t* d, uint32_t a) {
    asm volatile("ldmatrix.sync.aligned.m8n8.x4.shared.b16 {%0,%1,%2,%3}, [%4];"
                 : "=r"(d[0]), "=r"(d[1]), "=r"(d[2]), "=r"(d[3]) : "r"(a));
}
__device__ __forceinline__ void mma16816(float* d, const uint32_t* a,
                                         const uint32_t* b) {
    asm volatile(
        "mma.sync.aligned.m16n8k16.row.col.f32.f16.f16.f32 "
        "{%0,%1,%2,%3}, {%4,%5,%6,%7}, {%8,%9}, {%0,%1,%2,%3};"
        : "+f"(d[0]), "+f"(d[1]), "+f"(d[2]), "+f"(d[3])
        : "r"(a[0]), "r"(a[1]), "r"(a[2]), "r"(a[3]), "r"(b[0]), "r"(b[1]));
}
__device__ __forceinline__ void bar_init(uint32_t bar, uint32_t cnt) {
    asm volatile("mbarrier.init.shared.b64 [%0], %1;" :: "r"(bar), "r"(cnt)
                 : "memory");
}
__device__ __forceinline__ void bar_wait(uint32_t bar, uint32_t parity) {
    asm volatile(
        "{\n\t.reg .pred P;\n\t"
        "WL%=:\n\t"
        "mbarrier.try_wait.parity.shared.b64 P, [%0], %1;\n\t"
        "@P bra WD%=;\n\t"
        "bra WL%=;\n\t"
        "WD%=:\n\t}"
        :: "r"(bar), "r"(parity) : "memory");
}
__device__ __forceinline__ void bar_arrive(uint32_t bar) {
    asm volatile("mbarrier.arrive.shared.b64 _, [%0];" :: "r"(bar) : "memory");
}
__device__ __forceinline__ void cp_arrive_noinc(uint32_t bar) {
    asm volatile("cp.async.mbarrier.arrive.noinc.shared.b64 [%0];"
                 :: "r"(bar) : "memory");
}
__device__ __forceinline__ float sigmoid_f(float x) {
    return 1.0f / (1.0f + __expf(-x));
}
__device__ __forceinline__ float tanh_f(float x) {
    float e = __expf(2.0f * x);
    return 1.0f - 2.0f / (e + 1.0f);
}
// smem byte offset for (row, 16B-chunk), rows are 128B (8 chunks), xor swizzle
__device__ __forceinline__ uint32_t sw(int r, int c) {
    return (uint32_t)(r * 128 + ((c ^ (r & 7)) << 4));
}
// convert 8 fp32 (two float4) -> one uint4 of 8 fp16
__device__ __forceinline__ uint4 cvt8(const float4 v0, const float4 v1) {
    __half2 h0 = __floats2half2_rn(v0.x, v0.y);
    __half2 h1 = __floats2half2_rn(v0.z, v0.w);
    __half2 h2 = __floats2half2_rn(v1.x, v1.y);
    __half2 h3 = __floats2half2_rn(v1.z, v1.w);
    uint4 u;
    u.x = *reinterpret_cast<uint32_t*>(&h0);
    u.y = *reinterpret_cast<uint32_t*>(&h1);
    u.z = *reinterpret_cast<uint32_t*>(&h2);
    u.w = *reinterpret_cast<uint32_t*>(&h3);
    return u;
}

// ---------------------------------------------------------------------------
// merged pre-pass, 8-float units (2x LDG.128 -> 1x STG.128):
//  blocks [0,2048): A, 4 units/thread (MLP 8). blocks [2048,2560): W, 2 units.
__global__ void __launch_bounds__(256) convAW(const float* __restrict__ ph,
                                              const float* __restrict__ xin,
                                              const float* __restrict__ Wi,
                                              const float* __restrict__ Wf,
                                              const float* __restrict__ Wo,
                                              const float* __restrict__ Wg) {
    if (blockIdx.x < 2048) {
        const size_t idx = (size_t)blockIdx.x * 256 + threadIdx.x;  // 512K thr
        #pragma unroll
        for (int j = 0; j < 4; ++j) {
            const size_t i = idx + (size_t)j * 524288;              // 2M units
            const int row = (int)(i >> 7);                          // 128 units/row
            const int col = (int)(i & 127) * 8;
            const float* s = (col < 512) ? (ph + (size_t)row * 512 + col)
                                         : (xin + (size_t)row * 512 + (col - 512));
            const float4 v0 = *(const float4*)s;
            const float4 v1 = *(const float4*)(s + 4);
            *(uint4*)(g_A16 + i * 8) = cvt8(v0, v1);
        }
    } else {
        const size_t idx = (size_t)(blockIdx.x - 2048) * 256 + threadIdx.x;
        #pragma unroll
        for (int j = 0; j < 2; ++j) {
            const size_t i = idx + (size_t)j * 131072;              // 256K units
            const int orow = (int)(i >> 7);
            const int col  = (int)(i & 127) * 8;
            const int ht = orow >> 7, r = orow & 127;
            // gate-interleaved: gate = bits[3:4], h = b6*16 + b5*8 + b[0:2]
            const int gate = (r >> 3) & 3;
            const int h    = ((r >> 6) << 4) + (((r >> 5) & 1) << 3) + (r & 7);
            const int hrow = ht * 32 + h;
            const float* W = (gate == 0) ? Wi : (gate == 1) ? Wf
                           : (gate == 2) ? Wo : Wg;
            const float* s = W + (size_t)hrow * KD + col;
            const float4 v0 = *(const float4*)s;
            const float4 v1 = *(const float4*)(s + 4);
            *(uint4*)(g_W16 + i * 8) = cvt8(v0, v1);
        }
    }
}

// ---------------------------------------------------------------------------
__global__ void __launch_bounds__(256, 2)
lstm_fp16_gemm(const float* __restrict__ prev_c,
               const float* __restrict__ bi, const float* __restrict__ bf,
               const float* __restrict__ bo, const float* __restrict__ bg,
               float* __restrict__ h_out, float* __restrict__ c_out)
{
    extern __shared__ char smc[];
    const uint32_t sb = s2u(smc);
    const uint32_t FULLB  = sb + PIPE_OFF;        // full[s]  at +0,8,16
    const uint32_t EMPTYB = sb + PIPE_OFF + 24;   // empty[s] at +0,8,16

    const int tid = threadIdx.x;
    const int wid = tid >> 5;
    const int lid = tid & 31;
    const int hb  = blockIdx.x;            // 16 h-tiles (fastest: W hot in L2)
    const int mb  = blockIdx.y;            // 128 m-tiles
    const int wm  = wid >> 1;              // 0..3
    const int wn  = wid & 1;               // 0..1

    if (tid == 0) {
        #pragma unroll
        for (int s = 0; s < NST; ++s) {
            bar_init(FULLB  + 8 * s, 256);
            bar_init(EMPTYB + 8 * s, 256);
        }
    }
    __syncthreads();

    // ---- cp.async mapping: 8 threads cover one 128B row ---------------------
    const int cr = tid >> 3;               // 0..31
    const int cc = tid & 7;                // chunk 0..7
    const __half* gA = g_A16 + (size_t)(mb * 128) * KD + cc * 8;
    const __half* gB = g_W16 + (size_t)(hb * 128) * KD + cc * 8;

    auto produce = [&](int kt) {
        const int s2 = kt % NST;
        const uint32_t so = sb + (uint32_t)s2 * STAGE_BYTES;
        const int kcol = kt * BK;
        #pragma unroll
        for (int i = 0; i < 4; ++i) {
            const int r = cr + 32 * i;
            cp16(so + sw(r, cc),         gA + (size_t)r * KD + kcol);
            cp16(so + 16384 + sw(r, cc), gB + (size_t)r * KD + kcol);
        }
        cp_arrive_noinc(FULLB + 8 * s2);
    };

    produce(0);
    produce(1);

    // ---- accumulators pre-loaded with biases --------------------------------
    float acc[2][8][4];
    {
        const int hq = hb * 32 + wn * 16 + (lid & 3) * 2;
        #pragma unroll
        for (int ni = 0; ni < 8; ++ni) {
            const int gate = ni & 3;
            const int h = hq + ((ni >> 2) << 3);
            const float* bp = (gate == 0) ? bi : (gate == 1) ? bf
                            : (gate == 2) ? bo : bg;
            const float b0 = __ldg(&bp[h]);
            const float b1 = __ldg(&bp[h + 1]);
            #pragma unroll
            for (int mi = 0; mi < 2; ++mi) {
                acc[mi][ni][0] = b0; acc[mi][ni][1] = b1;
                acc[mi][ni][2] = b0; acc[mi][ni][3] = b1;
            }
        }
    }

    // ldmatrix lane coordinates
    const int a_r = (lid & 15);
    const int a_c = (lid >> 4);
    const int b_r = ((lid >> 4) << 3) + (lid & 7);
    const int b_c = ((lid >> 3) & 1);

    #pragma unroll 1
    for (int it = 0; it < NITER; ++it) {
        const int s = it % NST;
        const int u = it / NST;

        // producer for stage it+2 (wait for stage free, then fill)
        if (it + 2 < NITER) {
            const int i2 = it + 2;
            if (i2 >= NST) {
                const int u2 = i2 / NST;
                bar_wait(EMPTYB + 8 * (i2 % NST), (u2 - 1) & 1);
            }
            produce(i2);
        }

        // consumer: wait until ALL threads' copies for stage s landed
        bar_wait(FULLB + 8 * s, u & 1);

        const uint32_t smA = sb + (uint32_t)s * STAGE_BYTES;
        const uint32_t smB = smA + 16384;

        uint32_t a[2][2][4], b[2][8][2];   // double-buffered fragments
        {
            #pragma unroll
            for (int mi = 0; mi < 2; ++mi)
                ldm_x4(a[0][mi], smA + sw(wm * 32 + mi * 16 + a_r, a_c));
            #pragma unroll
            for (int n2 = 0; n2 < 4; ++n2) {
                uint32_t t4[4];
                ldm_x4(t4, smB + sw(wn * 64 + n2 * 16 + b_r, b_c));
                b[0][n2 * 2][0] = t4[0]; b[0][n2 * 2][1] = t4[1];
                b[0][n2 * 2 + 1][0] = t4[2]; b[0][n2 * 2 + 1][1] = t4[3];
            }
        }
        #pragma unroll
        for (int ks = 0; ks < 4; ++ks) {
            const int cur = ks & 1, nxt = cur ^ 1;
            if (ks < 3) {                  // preload ks+1 while mma'ing ks
                const int kc = (ks + 1) * 2;
                #pragma unroll
                for (int mi = 0; mi < 2; ++mi)
                    ldm_x4(a[nxt][mi], smA + sw(wm * 32 + mi * 16 + a_r, kc + a_c));
                #pragma unroll
                for (int n2 = 0; n2 < 4; ++n2) {
                    uint32_t t4[4];
                    ldm_x4(t4, smB + sw(wn * 64 + n2 * 16 + b_r, kc + b_c));
                    b[nxt][n2 * 2][0] = t4[0]; b[nxt][n2 * 2][1] = t4[1];
                    b[nxt][n2 * 2 + 1][0] = t4[2]; b[nxt][n2 * 2 + 1][1] = t4[3];
                }
            }
            #pragma unroll
            for (int mi = 0; mi < 2; ++mi)
                #pragma unroll
                for (int ni = 0; ni < 8; ++ni)
                    mma16816(acc[mi][ni], a[cur][mi], b[cur][ni]);
        }
        // all smem reads of stage s are complete (MMAs consumed the LDSM regs)
        bar_arrive(EMPTYB + 8 * s);
    }

    // ---- register-local epilogue --------------------------------------------
    #pragma unroll
    for (int mi = 0; mi < 2; ++mi) {
        const int r_base = mb * 128 + wm * 32 + mi * 16 + (lid >> 2);
        #pragma unroll
        for (int ho = 0; ho < 2; ++ho) {
            const int hg = hb * 32 + wn * 16 + ho * 8 + (lid & 3) * 2;
            #pragma unroll
            for (int pr = 0; pr < 2; ++pr) {       // row +0 / +8
                const int r = r_base + pr * 8;
                const size_t off = (size_t)r * HID + hg;
                const float2 pc = *(const float2*)(prev_c + off);
                const int q0 = pr * 2, q1 = pr * 2 + 1;
                const float i0 = sigmoid_f(acc[mi][ho * 4 + 0][q0]);
                const float f0 = sigmoid_f(acc[mi][ho * 4 + 1][q0]);
                const float o0 = sigmoid_f(acc[mi][ho * 4 + 2][q0]);
                const float g0 = tanh_f   (acc[mi][ho * 4 + 3][q0]);
                const float i1 = sigmoid_f(acc[mi][ho * 4 + 0][q1]);
                const float f1 = sigmoid_f(acc[mi][ho * 4 + 1][q1]);
                const float o1 = sigmoid_f(acc[mi][ho * 4 + 2][q1]);
                const float g1 = tanh_f   (acc[mi][ho * 4 + 3][q1]);
                const float c0 = f0 * pc.x + i0 * g0;
                const float c1 = f1 * pc.y + i1 * g1;
                *(float2*)(h_out + off) = make_float2(tanh_f(c0) * o0,
                                                      tanh_f(c1) * o1);
                *(float2*)(c_out + off) = make_float2(c0, c1);
            }
        }
    }
}

// ---------------------------------------------------------------------------
extern "C" void kernel_launch(void* const* d_in, const int* in_sizes, int n_in,
                              void* d_out, int out_size) {
    const float* input_ = (const float*)d_in[0];
    const float* prev_h = (const float*)d_in[1];
    const float* prev_c = (const float*)d_in[2];
    const float* W_i = (const float*)d_in[3];  const float* b_i = (const float*)d_in[4];
    const float* W_f = (const float*)d_in[5];  const float* b_f = (const float*)d_in[6];
    const float* W_g = (const float*)d_in[7];  const float* b_g = (const float*)d_in[8];
    const float* W_o = (const float*)d_in[9];  const float* b_o = (const float*)d_in[10];

    float* h_out = (float*)d_out;
    float* c_out = h_out + (size_t)BATCH * HID;

    convAW<<<2560, 256>>>(prev_h, input_, W_i, W_f, W_o, W_g);

    cudaFuncSetAttribute(lstm_fp16_gemm,
                         cudaFuncAttributeMaxDynamicSharedMemorySize, DYN_BYTES);
    dim3 grid(16, 128);
    lstm_fp16_gemm<<<grid, 256, DYN_BYTES>>>(prev_c, b_i, b_f, b_o, b_g,
                                             h_out, c_out);
}